// round 4
// baseline (speedup 1.0000x reference)
#include <cuda_runtime.h>
#include <math.h>

// Chamfer loss, B=4, C=3, Np=Ng=8192. R4:
//  R2 scalar core (known good) + wave-balance split (2048 blocks) +
//  software-pipelined gt staging + tree column reduce + padded cbuf.
// Per pair: e = fma(-2px,gx, fma(-2py,gy, fma(-2pz,gz, g2)));  d2 = e + p2
//   rowmin tracks e (p2 added once at end), colmin tracks e+p2.
// sqrt only on final mins (monotone). Both sides flushed via int atomicMin
// on positive clamped float bits (order-independent => deterministic).

#define BATCH   4
#define NPT     8192
#define TPQ     128                      // predict points per block
#define TGQ     128                      // gt points per stage
#define GSPLIT  8                        // g-range splits per batch
#define NSTAGES ((NPT / GSPLIT) / TGQ)   // 8
#define NTH     256                      // 16 (g=tx) x 16 (p=ty)
#define EPSF    1e-12f
#define FLTMAXI 0x7f7fffff

__device__ int g_colmin[BATCH * NPT];
__device__ int g_rowmin[BATCH * NPT];

__global__ void init_kernel() {
    int i = blockIdx.x * blockDim.x + threadIdx.x;
    if (i < BATCH * NPT) { g_colmin[i] = FLTMAXI; g_rowmin[i] = FLTMAXI; }
}

__global__ __launch_bounds__(NTH, 2)
void chamfer_main(const float* __restrict__ P, const float* __restrict__ G) {
    const int b     = blockIdx.z;
    const int pbase = blockIdx.x * TPQ;
    const int gbeg  = blockIdx.y * (NPT / GSPLIT);
    const float* Pb = P + (size_t)b * 3 * NPT;
    const float* Gb = G + (size_t)b * 3 * NPT;
    const int tid = threadIdx.x;
    const int tx  = tid & 15;        // g direction
    const int ty  = tid >> 4;        // p direction

    __shared__ float4 sp[TPQ];
    __shared__ float4 sg[TGQ];
    __shared__ float  cbuf[16][TGQ + 1];   // +1 pad: conflict-free stores

    // ---- prologue: prefetch stage-0 gt, load & transform p tile ----
    float rx = 0.f, ry = 0.f, rz = 0.f;
    if (tid < TGQ) {
        rx = Gb[gbeg + tid];
        ry = Gb[NPT + gbeg + tid];
        rz = Gb[2 * NPT + gbeg + tid];
    }
    for (int i = tid; i < TPQ; i += NTH) {
        float px = Pb[pbase + i];
        float py = Pb[NPT + pbase + i];
        float pz = Pb[2 * NPT + pbase + i];
        sp[i] = make_float4(-2.f * px, -2.f * py, -2.f * pz,
                            px * px + py * py + pz * pz);
    }
    if (tid < TGQ)
        sg[tid] = make_float4(rx, ry, rz, rx * rx + ry * ry + rz * rz);
    __syncthreads();

    float pa[8], pb_[8], pc[8], pp2[8], rowmin[8];
#pragma unroll
    for (int ii = 0; ii < 8; ii++) {
        float4 v = sp[ty * 8 + ii];
        pa[ii] = v.x; pb_[ii] = v.y; pc[ii] = v.z; pp2[ii] = v.w;
        rowmin[ii] = 3.4e38f;
    }

    for (int s = 0; s < NSTAGES; s++) {
        // prefetch next stage while this stage computes
        if (s + 1 < NSTAGES && tid < TGQ) {
            int g = gbeg + (s + 1) * TGQ + tid;
            rx = Gb[g]; ry = Gb[NPT + g]; rz = Gb[2 * NPT + g];
        }

        float gx[8], gy[8], gz[8], g2[8], colmin[8];
#pragma unroll
        for (int jj = 0; jj < 8; jj++) {
            float4 v = sg[jj * 16 + tx];
            gx[jj] = v.x; gy[jj] = v.y; gz[jj] = v.z; g2[jj] = v.w;
            colmin[jj] = 3.4e38f;
        }

#pragma unroll
        for (int ii = 0; ii < 8; ii++) {
#pragma unroll
            for (int jj = 0; jj < 8; jj++) {
                float e = fmaf(pc[ii], gz[jj], g2[jj]);
                e = fmaf(pb_[ii], gy[jj], e);
                e = fmaf(pa[ii], gx[jj], e);
                rowmin[ii] = fminf(rowmin[ii], e);
                colmin[jj] = fminf(colmin[jj], e + pp2[ii]);
            }
        }

        // column reduce across the 16 ty threads sharing each g column
#pragma unroll
        for (int jj = 0; jj < 8; jj++)
            cbuf[ty][jj * 16 + tx] = colmin[jj];
        __syncthreads();

        if (tid < TGQ) {
            float v[16];
#pragma unroll
            for (int t = 0; t < 16; t++) v[t] = cbuf[t][tid];
#pragma unroll
            for (int st = 8; st > 0; st >>= 1)
#pragma unroll
                for (int t = 0; t < 8; t++)
                    if (t < st) v[t] = fminf(v[t], v[t + st]);
            float m = fmaxf(v[0], EPSF);   // clamp (ref) + positive => int order valid
            atomicMin(&g_colmin[b * NPT + gbeg + s * TGQ + tid], __float_as_int(m));
        }

        // stage s+1 -> smem (prefetch regs have landed; same barrier window)
        if (s + 1 < NSTAGES && tid < TGQ)
            sg[tid] = make_float4(rx, ry, rz, rx * rx + ry * ry + rz * rz);
        __syncthreads();
    }

    // row-min reduce across tx: lanes differing in low 4 bits share ty and
    // partition g columns -> xor-shuffle over 1,2,4,8 completes the min.
#pragma unroll
    for (int ii = 0; ii < 8; ii++) {
        float m = rowmin[ii];
#pragma unroll
        for (int off = 1; off < 16; off <<= 1)
            m = fminf(m, __shfl_xor_sync(0xffffffffu, m, off));
        if (tx == 0) {
            m = fmaxf(m + pp2[ii], EPSF);
            atomicMin(&g_rowmin[b * NPT + pbase + ty * 8 + ii], __float_as_int(m));
        }
    }
}

__global__ void finalize_kernel(float* out) {
    __shared__ float sred[256];
    const int tid = threadIdx.x;
    float s = 0.f;
    for (int i = tid; i < BATCH * NPT; i += 256) {
        s += sqrtf(__int_as_float(g_colmin[i]));   // already clamped >= EPS
        s += sqrtf(__int_as_float(g_rowmin[i]));
    }
    sred[tid] = s;
    __syncthreads();
    for (int st = 128; st > 0; st >>= 1) {
        if (tid < st) sred[tid] += sred[tid + st];
        __syncthreads();
    }
    if (tid == 0)
        out[0] = sred[0] / (float)(BATCH * 2 * NPT);   // denom = B*(Np+Ng)
}

extern "C" void kernel_launch(void* const* d_in, const int* in_sizes, int n_in,
                              void* d_out, int out_size) {
    const float* P = (const float*)d_in[0];
    const float* G = (const float*)d_in[1];

    init_kernel<<<(BATCH * NPT + 255) / 256, 256>>>();

    dim3 grid(NPT / TPQ, GSPLIT, BATCH);   // 64 x 8 x 4 = 2048 blocks
    chamfer_main<<<grid, NTH>>>(P, G);

    finalize_kernel<<<1, 256>>>((float*)d_out);
}

// round 5
// speedup vs baseline: 1.2602x; 1.2602x over previous
#include <cuda_runtime.h>
#include <math.h>

// Chamfer loss, B=4, C=3, Np=Ng=8192. R5:
//  R2 core (256 blocks, single wave at occ 2) +
//  double-buffered sg/cbuf -> ONE __syncthreads per stage +
//  register prefetch of next gt chunk +
//  pad kernel so ncu -s 5 -c 1 lands on chamfer_main.
// Per pair: e = fma(-2px,gx, fma(-2py,gy, fma(-2pz,gz, g2)));  d2 = e + p2
// sqrt only on final mins (monotone). Col-min via int atomicMin on positive
// clamped float bits (order-independent => deterministic).

#define BATCH   4
#define NPT     8192
#define TPQ     128                      // predict points per block
#define TGQ     128                      // gt points per stage
#define NSTAGES (NPT / TGQ)              // 64
#define NTH     256                      // 16 (g=tx) x 16 (p=ty)
#define EPSF    1e-12f
#define FLTMAXI 0x7f7fffff

__device__ int   g_colmin[BATCH * NPT];
__device__ float g_rowsum[BATCH * (NPT / TPQ)];

__global__ void init_kernel() {
    int i = blockIdx.x * blockDim.x + threadIdx.x;
    if (i < BATCH * NPT) g_colmin[i] = FLTMAXI;
}

__global__ void pad_kernel() {}   // shifts ncu -s 5 onto chamfer_main

__global__ __launch_bounds__(NTH, 2)
void chamfer_main(const float* __restrict__ P, const float* __restrict__ G) {
    const int b     = blockIdx.y;
    const int pbase = blockIdx.x * TPQ;
    const float* Pb = P + (size_t)b * 3 * NPT;
    const float* Gb = G + (size_t)b * 3 * NPT;
    const int tid = threadIdx.x;
    const int tx  = tid & 15;        // g direction
    const int ty  = tid >> 4;        // p direction

    __shared__ float4 sp[TPQ];
    __shared__ float4 sg[2][TGQ];               // double buffer
    __shared__ float  cbuf[2][16][TGQ + 1];     // double buffer, padded

    // ---- prologue: prefetch stage-0 gt, load & transform p tile ----
    float rx = 0.f, ry = 0.f, rz = 0.f;
    if (tid < TGQ) {
        rx = Gb[tid];
        ry = Gb[NPT + tid];
        rz = Gb[2 * NPT + tid];
    }
    for (int i = tid; i < TPQ; i += NTH) {
        float px = Pb[pbase + i];
        float py = Pb[NPT + pbase + i];
        float pz = Pb[2 * NPT + pbase + i];
        sp[i] = make_float4(-2.f * px, -2.f * py, -2.f * pz,
                            px * px + py * py + pz * pz);
    }
    if (tid < TGQ)
        sg[0][tid] = make_float4(rx, ry, rz, rx * rx + ry * ry + rz * rz);
    __syncthreads();

    float pa[8], pb_[8], pc[8], pp2[8], rowmin[8];
#pragma unroll
    for (int ii = 0; ii < 8; ii++) {
        float4 v = sp[ty * 8 + ii];
        pa[ii] = v.x; pb_[ii] = v.y; pc[ii] = v.z; pp2[ii] = v.w;
        rowmin[ii] = 3.4e38f;
    }

    for (int s = 0; s < NSTAGES; s++) {
        const int cur = s & 1, nxt = cur ^ 1;

        // issue next-stage gmem loads now; latency hidden under compute
        if (s + 1 < NSTAGES && tid < TGQ) {
            int g = (s + 1) * TGQ + tid;
            rx = Gb[g]; ry = Gb[NPT + g]; rz = Gb[2 * NPT + g];
        }

        float gx[8], gy[8], gz[8], g2[8], colmin[8];
#pragma unroll
        for (int jj = 0; jj < 8; jj++) {
            float4 v = sg[cur][jj * 16 + tx];
            gx[jj] = v.x; gy[jj] = v.y; gz[jj] = v.z; g2[jj] = v.w;
            colmin[jj] = 3.4e38f;
        }

#pragma unroll
        for (int ii = 0; ii < 8; ii++) {
#pragma unroll
            for (int jj = 0; jj < 8; jj++) {
                float e = fmaf(pc[ii], gz[jj], g2[jj]);
                e = fmaf(pb_[ii], gy[jj], e);
                e = fmaf(pa[ii], gx[jj], e);
                rowmin[ii] = fminf(rowmin[ii], e);
                colmin[jj] = fminf(colmin[jj], e + pp2[ii]);
            }
        }

        // stage s+1 gt chunk -> other smem buffer (prefetch regs landed)
        if (s + 1 < NSTAGES && tid < TGQ)
            sg[nxt][tid] = make_float4(rx, ry, rz, rx * rx + ry * ry + rz * rz);

        // per-warp column partials -> cbuf[cur]
#pragma unroll
        for (int jj = 0; jj < 8; jj++)
            cbuf[cur][ty][jj * 16 + tx] = colmin[jj];

        __syncthreads();   // the ONLY barrier per stage

        // column reduce overlaps next stage's compute in the other warps
        if (tid < TGQ) {
            float v[16];
#pragma unroll
            for (int t = 0; t < 16; t++) v[t] = cbuf[cur][t][tid];
#pragma unroll
            for (int st = 8; st > 0; st >>= 1)
#pragma unroll
                for (int t = 0; t < 8; t++)
                    if (t < st) v[t] = fminf(v[t], v[t + st]);
            float m = fmaxf(v[0], EPSF);   // clamp (ref); positive => int order valid
            atomicMin(&g_colmin[b * NPT + s * TGQ + tid], __float_as_int(m));
        }
    }

    // row-min reduce across tx: lanes differing in low 4 bits share ty and
    // partition g columns -> xor-shuffle over 1,2,4,8 completes the min.
#pragma unroll
    for (int ii = 0; ii < 8; ii++) {
        float m = rowmin[ii];
#pragma unroll
        for (int off = 1; off < 16; off <<= 1)
            m = fminf(m, __shfl_xor_sync(0xffffffffu, m, off));
        rowmin[ii] = m;
    }

    float rsum = 0.f;
    if (tx == 0) {
#pragma unroll
        for (int ii = 0; ii < 8; ii++)
            rsum += sqrtf(fmaxf(rowmin[ii] + pp2[ii], EPSF));
    }

    __shared__ float sred[NTH];
    sred[tid] = rsum;
    __syncthreads();
    for (int st = NTH / 2; st > 0; st >>= 1) {
        if (tid < st) sred[tid] += sred[tid + st];
        __syncthreads();
    }
    if (tid == 0)
        g_rowsum[b * gridDim.x + blockIdx.x] = sred[0];
}

__global__ void finalize_kernel(float* out, int nblocks) {
    __shared__ float sred[256];
    const int tid = threadIdx.x;
    float s = 0.f;
    for (int i = tid; i < BATCH * NPT; i += 256)
        s += sqrtf(__int_as_float(g_colmin[i]));   // already clamped >= EPS
    for (int i = tid; i < nblocks; i += 256)
        s += g_rowsum[i];
    sred[tid] = s;
    __syncthreads();
    for (int st = 128; st > 0; st >>= 1) {
        if (tid < st) sred[tid] += sred[tid + st];
        __syncthreads();
    }
    if (tid == 0)
        out[0] = sred[0] / (float)(BATCH * 2 * NPT);   // denom = B*(Np+Ng)
}

extern "C" void kernel_launch(void* const* d_in, const int* in_sizes, int n_in,
                              void* d_out, int out_size) {
    const float* P = (const float*)d_in[0];
    const float* G = (const float*)d_in[1];

    init_kernel<<<(BATCH * NPT + 255) / 256, 256>>>();

    dim3 grid(NPT / TPQ, BATCH);             // 64 x 4 = 256 blocks, single wave
    chamfer_main<<<grid, NTH>>>(P, G);

    finalize_kernel<<<1, 256>>>((float*)d_out, BATCH * (NPT / TPQ));

    pad_kernel<<<1, 32>>>();   // 4-launch period => ncu -s 5 profiles chamfer_main
}